// round 4
// baseline (speedup 1.0000x reference)
#include <cuda_runtime.h>
#include <math.h>

#define NMAX 50000
#define EMAX 800000

typedef unsigned long long u64t;

__device__ __forceinline__ u64t ffma2(u64t a, u64t b, u64t c) {
    u64t d;
    asm("fma.rn.f32x2 %0, %1, %2, %3;" : "=l"(d) : "l"(a), "l"(b), "l"(c));
    return d;
}

// ---------------- scratch (device globals; no allocation allowed) ----------------
__device__ __align__(16) float g_gx[NMAX * 96];      // gconv(x) for all T: [n][f][t]
__device__ __align__(16) float g_h0[NMAX * 64];
__device__ __align__(16) float g_h1[NMAX * 64];
__device__ __align__(16) float g_gpair[NMAX * 128];  // [gconv(h0) | gconv(h1)]
__device__ __align__(16) float g_rh[NMAX * 64];      // r * h
__device__ __align__(16) float g_grh[NMAX * 64];     // gconv(r*h)
__device__ __align__(16) float g_z[NMAX * 64];
__device__ int   g_rowptr[NMAX + 1];
__device__ int   g_off[NMAX];
__device__ int   g_srcs[EMAX];
__device__ float g_ws[EMAX];

// ---------------- CSR build ----------------
__global__ void zero_rowptr(int n) {
    int i = blockIdx.x * blockDim.x + threadIdx.x;
    if (i < n + 1) g_rowptr[i] = 0;
}

__global__ void hist_kernel(const int* __restrict__ dst, int E) {
    int e = blockIdx.x * blockDim.x + threadIdx.x;
    if (e < E) atomicAdd(&g_rowptr[dst[e] + 1], 1);
}

// single-block inclusive scan of g_rowptr[0..n]
__global__ void scan_kernel(int n) {
    __shared__ int buf[1024];
    __shared__ int carry;
    if (threadIdx.x == 0) carry = 0;
    __syncthreads();
    for (int base = 0; base < n + 1; base += 1024) {
        int i = base + threadIdx.x;
        int v = (i < n + 1) ? g_rowptr[i] : 0;
        buf[threadIdx.x] = v;
        __syncthreads();
        for (int ofs = 1; ofs < 1024; ofs <<= 1) {
            int t = (threadIdx.x >= ofs) ? buf[threadIdx.x - ofs] : 0;
            __syncthreads();
            buf[threadIdx.x] += t;
            __syncthreads();
        }
        int inc = buf[threadIdx.x] + carry;
        if (i < n + 1) g_rowptr[i] = inc;
        __syncthreads();
        if (threadIdx.x == 1023) carry = inc;
        __syncthreads();
    }
}

__global__ void copy_off(int n) {
    int i = blockIdx.x * blockDim.x + threadIdx.x;
    if (i < n) g_off[i] = g_rowptr[i];
}

__global__ void scatter_kernel(const int* __restrict__ src, const int* __restrict__ dst,
                               const float* __restrict__ w, int E) {
    int e = blockIdx.x * blockDim.x + threadIdx.x;
    if (e < E) {
        int p = atomicAdd(&g_off[dst[e]], 1);
        g_srcs[p] = src[e];
        g_ws[p]   = w[e];
    }
}

// ---------------- graph convolutions (warp per node, CSR) ----------------
__global__ void gconv_x(const float* __restrict__ x, int N) {
    int node = blockIdx.x * (blockDim.x >> 5) + (threadIdx.x >> 5);
    if (node >= N) return;
    int lane = threadIdx.x & 31;
    int s = g_rowptr[node], e = g_rowptr[node + 1];
    float a0 = 0.f, a1 = 0.f, a2 = 0.f;
    for (int i = s; i < e; i++) {
        int sn = __ldg(&g_srcs[i]);
        float w = __ldg(&g_ws[i]);
        const float* f = x + (size_t)sn * 96;
        a0 += w * __ldg(f + lane);
        a1 += w * __ldg(f + lane + 32);
        a2 += w * __ldg(f + lane + 64);
    }
    float* o = g_gx + (size_t)node * 96;
    o[lane] = a0; o[lane + 32] = a1; o[lane + 64] = a2;
}

__global__ void gconv64_k(const float* __restrict__ feat, float* __restrict__ out, int N) {
    int node = blockIdx.x * (blockDim.x >> 5) + (threadIdx.x >> 5);
    if (node >= N) return;
    int lane = threadIdx.x & 31;
    int s = g_rowptr[node], e = g_rowptr[node + 1];
    float ax = 0.f, ay = 0.f;
    int i = s;
    for (; i + 1 < e; i += 2) {
        int s0 = __ldg(&g_srcs[i]), s1 = __ldg(&g_srcs[i + 1]);
        float w0 = __ldg(&g_ws[i]), w1 = __ldg(&g_ws[i + 1]);
        float2 f0 = __ldg(((const float2*)(feat + (size_t)s0 * 64)) + lane);
        float2 f1 = __ldg(((const float2*)(feat + (size_t)s1 * 64)) + lane);
        ax += w0 * f0.x; ay += w0 * f0.y;
        ax += w1 * f1.x; ay += w1 * f1.y;
    }
    if (i < e) {
        int s0 = __ldg(&g_srcs[i]);
        float w0 = __ldg(&g_ws[i]);
        float2 f0 = __ldg(((const float2*)(feat + (size_t)s0 * 64)) + lane);
        ax += w0 * f0.x; ay += w0 * f0.y;
    }
    ((float2*)(out + (size_t)node * 64))[lane] = make_float2(ax, ay);
}

// aggregate two 64-col tables in one edge pass -> out row of 128 ([a | b])
__global__ void gconv_dual_k(const float* __restrict__ fa, const float* __restrict__ fb,
                             float* __restrict__ out, int N) {
    int node = blockIdx.x * (blockDim.x >> 5) + (threadIdx.x >> 5);
    if (node >= N) return;
    int lane = threadIdx.x & 31;
    int s = g_rowptr[node], e = g_rowptr[node + 1];
    float ax = 0.f, ay = 0.f, bx = 0.f, by = 0.f;
    int i = s;
    for (; i + 1 < e; i += 2) {
        int s0 = __ldg(&g_srcs[i]), s1 = __ldg(&g_srcs[i + 1]);
        float w0 = __ldg(&g_ws[i]), w1 = __ldg(&g_ws[i + 1]);
        float2 fa0 = __ldg(((const float2*)(fa + (size_t)s0 * 64)) + lane);
        float2 fb0 = __ldg(((const float2*)(fb + (size_t)s0 * 64)) + lane);
        float2 fa1 = __ldg(((const float2*)(fa + (size_t)s1 * 64)) + lane);
        float2 fb1 = __ldg(((const float2*)(fb + (size_t)s1 * 64)) + lane);
        ax += w0 * fa0.x; ay += w0 * fa0.y; bx += w0 * fb0.x; by += w0 * fb0.y;
        ax += w1 * fa1.x; ay += w1 * fa1.y; bx += w1 * fb1.x; by += w1 * fb1.y;
    }
    if (i < e) {
        int s0 = __ldg(&g_srcs[i]);
        float w0 = __ldg(&g_ws[i]);
        float2 fa0 = __ldg(((const float2*)(fa + (size_t)s0 * 64)) + lane);
        float2 fb0 = __ldg(((const float2*)(fb + (size_t)s0 * 64)) + lane);
        ax += w0 * fa0.x; ay += w0 * fa0.y; bx += w0 * fb0.x; by += w0 * fb0.y;
    }
    ((float2*)(out + (size_t)node * 128))[lane]       = make_float2(ax, ay);
    ((float2*)(out + (size_t)node * 128 + 64))[lane]  = make_float2(bx, by);
}

// ---------------- fused gate GEMM (FFMA2): rz = sigmoid([A1|A2] @ W + b); emit rh, z ----
// block: 256 threads, tile 64 rows x 128 cols; thread: 8 rows x 4 cols
// SW layout: paired over k: SW[kp*256 + c*2 + s] = W[(2kp+s)*128 + c]
__global__ void __launch_bounds__(256) gate_kernel(
        const float* __restrict__ A1, int lda1, int cda1, int K1,
        const float* __restrict__ A2, int lda2, int K2,
        const float* __restrict__ W, const float* __restrict__ bias,
        const float* __restrict__ h,
        float* __restrict__ rh, float* __restrict__ z, int nrows) {
    extern __shared__ float sh[];
    const int K = K1 + K2, KP = K + 2;          // KP even -> 8B-aligned float2 rows
    float* SW = sh;              // K * 128 (paired layout)
    float* SA = sh + K * 128;    // 64 * KP
    int tid = threadIdx.x;
    for (int idx = tid; idx < K * 128; idx += 256) {
        int k = idx >> 7, c = idx & 127;
        SW[(k >> 1) * 256 + c * 2 + (k & 1)] = W[idx];
    }
    int row0 = blockIdx.x * 64;
    for (int idx = tid; idx < 64 * K; idx += 256) {
        int r = idx / K, k = idx - r * K;
        int grow = row0 + r;
        float v = 0.f;
        if (grow < nrows)
            v = (k < K1) ? __ldg(&A1[(size_t)grow * lda1 + k * cda1])
                         : __ldg(&A2[(size_t)grow * lda2 + (k - K1)]);
        SA[r * KP + k] = v;
    }
    __syncthreads();
    int colg = (tid & 31) * 4, rowg = (tid >> 5) * 8;
    u64t acc[8][4];
#pragma unroll
    for (int r = 0; r < 8; r++) { acc[r][0] = acc[r][1] = acc[r][2] = acc[r][3] = 0ull; }
    const int KH = K >> 1;
#pragma unroll 2
    for (int kp = 0; kp < KH; kp++) {
        ulonglong2 wA = *(const ulonglong2*)&SW[kp * 256 + colg * 2];
        ulonglong2 wB = *(const ulonglong2*)&SW[kp * 256 + colg * 2 + 4];
#pragma unroll
        for (int r = 0; r < 8; r++) {
            u64t a2 = *(const u64t*)&SA[(rowg + r) * KP + 2 * kp];
            acc[r][0] = ffma2(a2, wA.x, acc[r][0]);
            acc[r][1] = ffma2(a2, wA.y, acc[r][1]);
            acc[r][2] = ffma2(a2, wB.x, acc[r][2]);
            acc[r][3] = ffma2(a2, wB.y, acc[r][3]);
        }
    }
#pragma unroll
    for (int r = 0; r < 8; r++) {
        int grow = row0 + rowg + r;
        if (grow >= nrows) break;
#pragma unroll
        for (int c = 0; c < 4; c++) {
            int j = colg + c;
            float2 p = *(float2*)&acc[r][c];
            float v = p.x + p.y + __ldg(&bias[j]);
            v = 1.f / (1.f + __expf(-v));
            if (j < 64) rh[(size_t)grow * 64 + j] = v * h[(size_t)grow * 64 + j];
            else        z[(size_t)grow * 64 + (j - 64)] = v;
        }
    }
}

// ---------------- fused candidate GEMM (FFMA2): c = tanh([A1|A2] @ W + b); h = z*h+(1-z)*c
// block: 256 threads, tile 128 rows x 64 cols; thread: 8 rows x 4 cols
__global__ void __launch_bounds__(256) cand_kernel(
        const float* __restrict__ A1, int lda1, int cda1, int K1,
        const float* __restrict__ A2, int lda2, int K2,
        const float* __restrict__ W, const float* __restrict__ bias,
        const float* __restrict__ z,
        float* __restrict__ h, int nrows) {
    extern __shared__ float sh[];
    const int K = K1 + K2, KP = K + 2;
    float* SW = sh;              // K * 64 (paired layout)
    float* SA = sh + K * 64;     // 128 * KP
    int tid = threadIdx.x;
    for (int idx = tid; idx < K * 64; idx += 256) {
        int k = idx >> 6, c = idx & 63;
        SW[(k >> 1) * 128 + c * 2 + (k & 1)] = W[idx];
    }
    int row0 = blockIdx.x * 128;
    for (int idx = tid; idx < 128 * K; idx += 256) {
        int r = idx / K, k = idx - r * K;
        int grow = row0 + r;
        float v = 0.f;
        if (grow < nrows)
            v = (k < K1) ? __ldg(&A1[(size_t)grow * lda1 + k * cda1])
                         : __ldg(&A2[(size_t)grow * lda2 + (k - K1)]);
        SA[r * KP + k] = v;
    }
    __syncthreads();
    int colg = (tid & 15) * 4, rowg = (tid >> 4) * 8;
    u64t acc[8][4];
#pragma unroll
    for (int r = 0; r < 8; r++) { acc[r][0] = acc[r][1] = acc[r][2] = acc[r][3] = 0ull; }
    const int KH = K >> 1;
#pragma unroll 2
    for (int kp = 0; kp < KH; kp++) {
        ulonglong2 wA = *(const ulonglong2*)&SW[kp * 128 + colg * 2];
        ulonglong2 wB = *(const ulonglong2*)&SW[kp * 128 + colg * 2 + 4];
#pragma unroll
        for (int r = 0; r < 8; r++) {
            u64t a2 = *(const u64t*)&SA[(rowg + r) * KP + 2 * kp];
            acc[r][0] = ffma2(a2, wA.x, acc[r][0]);
            acc[r][1] = ffma2(a2, wA.y, acc[r][1]);
            acc[r][2] = ffma2(a2, wB.x, acc[r][2]);
            acc[r][3] = ffma2(a2, wB.y, acc[r][3]);
        }
    }
#pragma unroll
    for (int r = 0; r < 8; r++) {
        int grow = row0 + rowg + r;
        if (grow >= nrows) break;
#pragma unroll
        for (int c = 0; c < 4; c++) {
            int j = colg + c;
            float2 p = *(float2*)&acc[r][c];
            float cv = tanhf(p.x + p.y + __ldg(&bias[j]));
            float zz = z[(size_t)grow * 64 + j];
            float hv = h[(size_t)grow * 64 + j];
            h[(size_t)grow * 64 + j] = zz * hv + (1.f - zz) * cv;
        }
    }
}

// ---------------- output: out = h1 @ Wout + bout (Wout is 64x1) ----------------
__global__ void out_kernel(const float* __restrict__ h1, const float* __restrict__ Wout,
                           const float* __restrict__ bout, float* __restrict__ out, int N) {
    int node = blockIdx.x * (blockDim.x >> 5) + (threadIdx.x >> 5);
    if (node >= N) return;
    int lane = threadIdx.x & 31;
    float v = h1[(size_t)node * 64 + lane] * __ldg(&Wout[lane]) +
              h1[(size_t)node * 64 + lane + 32] * __ldg(&Wout[lane + 32]);
#pragma unroll
    for (int o = 16; o > 0; o >>= 1) v += __shfl_xor_sync(0xffffffffu, v, o);
    if (lane == 0) out[node] = v + bout[0];
}

// ---------------- launch ----------------
extern "C" void kernel_launch(void* const* d_in, const int* in_sizes, int n_in,
                              void* d_out, int out_size) {
    const float* x   = (const float*)d_in[0];
    const int*   ei  = (const int*)d_in[1];
    const float* ew  = (const float*)d_in[2];
    const float* Wg0 = (const float*)d_in[3];
    const float* bg0 = (const float*)d_in[4];
    const float* Wc0 = (const float*)d_in[5];
    const float* bc0 = (const float*)d_in[6];
    const float* Wg1 = (const float*)d_in[7];
    const float* bg1 = (const float*)d_in[8];
    const float* Wc1 = (const float*)d_in[9];
    const float* bc1 = (const float*)d_in[10];
    const float* Wout = (const float*)d_in[11];
    const float* bout = (const float*)d_in[12];

    int N = in_sizes[0] / 96;   // F=8, T=12
    int E = in_sizes[2];
    if (N > NMAX || E > EMAX) return;
    const int* src = ei;
    const int* dst = ei + E;

    float *p_gx, *p_h0, *p_h1, *p_gpair, *p_rh, *p_grh, *p_z;
    cudaGetSymbolAddress((void**)&p_gx, g_gx);
    cudaGetSymbolAddress((void**)&p_h0, g_h0);
    cudaGetSymbolAddress((void**)&p_h1, g_h1);
    cudaGetSymbolAddress((void**)&p_gpair, g_gpair);
    cudaGetSymbolAddress((void**)&p_rh, g_rh);
    cudaGetSymbolAddress((void**)&p_grh, g_grh);
    cudaGetSymbolAddress((void**)&p_z, g_z);

    cudaFuncSetAttribute(gate_kernel, cudaFuncAttributeMaxDynamicSharedMemorySize, 103424);
    cudaFuncSetAttribute(cand_kernel, cudaFuncAttributeMaxDynamicSharedMemorySize, 103424);

    // init state (gpair's first half doubles as gconv(h0)=0 for step 0)
    cudaMemsetAsync(p_h0, 0, (size_t)N * 64 * sizeof(float));
    cudaMemsetAsync(p_h1, 0, (size_t)N * 64 * sizeof(float));
    cudaMemsetAsync(p_gpair, 0, (size_t)N * 128 * sizeof(float));

    // CSR build (by dst)
    zero_rowptr<<<(N + 1 + 255) / 256, 256>>>(N);
    hist_kernel<<<(E + 255) / 256, 256>>>(dst, E);
    scan_kernel<<<1, 1024>>>(N);
    copy_off<<<(N + 255) / 256, 256>>>(N);
    scatter_kernel<<<(E + 255) / 256, 256>>>(src, dst, ew, E);

    // precompute gconv(x) for all timesteps (96 cols, one edge pass)
    int gblocks = (N + 7) / 8;
    gconv_x<<<gblocks, 256>>>(x, N);

    size_t sm_g0 = (size_t)(72 * 128 + 64 * 74) * 4;    // gate cell0 (K=72)
    size_t sm_g1 = (size_t)(128 * 128 + 64 * 130) * 4;  // gate cell1 (K=128)
    size_t sm_c0 = (size_t)(72 * 64 + 128 * 74) * 4;    // cand cell0 (K=72)
    size_t sm_c1 = (size_t)(128 * 64 + 128 * 130) * 4;  // cand cell1 (K=128)
    int gate_blocks = (N + 63) / 64;
    int cand_blocks = (N + 127) / 128;

    for (int t = 0; t < 12; t++) {
        // ---- cell 0 ----  (gconv(h0_{t-1}) lives in gpair[:, 0:64] from prior dual pass)
        gate_kernel<<<gate_blocks, 256, sm_g0>>>(p_gx + t, 96, 12, 8,
                                                 p_gpair, 128, 64,
                                                 Wg0, bg0, p_h0, p_rh, p_z, N);
        gconv64_k<<<gblocks, 256>>>(p_rh, p_grh, N);
        cand_kernel<<<cand_blocks, 256, sm_c0>>>(p_gx + t, 96, 12, 8,
                                                 p_grh, 64, 64,
                                                 Wc0, bc0, p_z, p_h0, N);  // h0 <- new h0
        // ---- cell 1 ----
        gconv_dual_k<<<gblocks, 256>>>(p_h0, p_h1, p_gpair, N);  // [gconv(h0_new) | gconv(h1)]
        gate_kernel<<<gate_blocks, 256, sm_g1>>>(p_gpair, 128, 1, 64,
                                                 p_gpair + 64, 128, 64,
                                                 Wg1, bg1, p_h1, p_rh, p_z, N);
        gconv64_k<<<gblocks, 256>>>(p_rh, p_grh, N);
        cand_kernel<<<cand_blocks, 256, sm_c1>>>(p_gpair, 128, 1, 64,
                                                 p_grh, 64, 64,
                                                 Wc1, bc1, p_z, p_h1, N);  // h1 <- new h1
    }

    out_kernel<<<gblocks, 256>>>(p_h1, Wout, bout, (float*)d_out, N);
}

// round 6
// speedup vs baseline: 1.3344x; 1.3344x over previous
#include <cuda_runtime.h>
#include <math.h>

#define NMAX 50000
#define EMAX 800000

__device__ __forceinline__ float tanh_fast(float x) {
    float y;
    asm("tanh.approx.f32 %0, %1;" : "=f"(y) : "f"(x));
    return y;
}
__device__ __forceinline__ float sigmoid_fast(float x) {
    return 0.5f * tanh_fast(0.5f * x) + 0.5f;
}

// ---------------- scratch (device globals; no allocation allowed) ----------------
__device__ __align__(16) float g_gx[NMAX * 96];      // gconv(x), t-major: [t][node][f]
__device__ __align__(16) float g_h0[NMAX * 64];
__device__ __align__(16) float g_h1[NMAX * 64];
__device__ __align__(16) float g_gpair[NMAX * 128];  // [gconv(h0) | gconv(h1)]
__device__ __align__(16) float g_rh[NMAX * 64];      // r * h
__device__ __align__(16) float g_grh[NMAX * 64];     // gconv(r*h)
__device__ __align__(16) float g_z[NMAX * 64];
__device__ int   g_rowptr[NMAX + 1];
__device__ int   g_off[NMAX];
__device__ int   g_srcs[EMAX];
__device__ float g_ws[EMAX];

// ---------------- init: zero h0, h1, gpair, rowptr in one kernel ----------------
__global__ void init_kernel(int N) {
    int stride = gridDim.x * blockDim.x;
    for (int i = blockIdx.x * blockDim.x + threadIdx.x; i < N * 128; i += stride) {
        g_gpair[i] = 0.f;
        if (i < N * 64) { g_h0[i] = 0.f; g_h1[i] = 0.f; }
        if (i < N + 1) g_rowptr[i] = 0;
    }
}

__global__ void hist_kernel(const int* __restrict__ dst, int E) {
    int e = blockIdx.x * blockDim.x + threadIdx.x;
    if (e < E) atomicAdd(&g_rowptr[dst[e] + 1], 1);
}

// single-block inclusive scan of g_rowptr[0..n]; also writes g_off
__global__ void scan_kernel(int n) {
    __shared__ int buf[1024];
    __shared__ int carry;
    if (threadIdx.x == 0) carry = 0;
    __syncthreads();
    for (int base = 0; base < n + 1; base += 1024) {
        int i = base + threadIdx.x;
        int v = (i < n + 1) ? g_rowptr[i] : 0;
        buf[threadIdx.x] = v;
        __syncthreads();
        for (int ofs = 1; ofs < 1024; ofs <<= 1) {
            int t = (threadIdx.x >= ofs) ? buf[threadIdx.x - ofs] : 0;
            __syncthreads();
            buf[threadIdx.x] += t;
            __syncthreads();
        }
        int inc = buf[threadIdx.x] + carry;
        if (i < n + 1) {
            g_rowptr[i] = inc;
            if (i < n) g_off[i] = inc;
        }
        __syncthreads();
        if (threadIdx.x == 1023) carry = inc;
        __syncthreads();
    }
}

__global__ void scatter_kernel(const int* __restrict__ src, const int* __restrict__ dst,
                               const float* __restrict__ w, int E) {
    int e = blockIdx.x * blockDim.x + threadIdx.x;
    if (e < E) {
        int p = atomicAdd(&g_off[dst[e]], 1);
        g_srcs[p] = src[e];
        g_ws[p]   = w[e];
    }
}

// ---------------- graph convolutions (warp per node, CSR) ----------------
// writes t-major: g_gx[t*N*8 + node*8 + f]
__global__ void gconv_x(const float* __restrict__ x, int N) {
    int node = blockIdx.x * (blockDim.x >> 5) + (threadIdx.x >> 5);
    if (node >= N) return;
    int lane = threadIdx.x & 31;
    int s = g_rowptr[node], e = g_rowptr[node + 1];
    float a0 = 0.f, a1 = 0.f, a2 = 0.f;
    for (int i = s; i < e; i++) {
        int sn = __ldg(&g_srcs[i]);
        float w = __ldg(&g_ws[i]);
        const float* f = x + (size_t)sn * 96;
        a0 += w * __ldg(f + lane);
        a1 += w * __ldg(f + lane + 32);
        a2 += w * __ldg(f + lane + 64);
    }
    size_t N8 = (size_t)N * 8;
#pragma unroll
    for (int j = 0; j < 3; j++) {
        int v = lane + j * 32;
        float a = (j == 0) ? a0 : (j == 1) ? a1 : a2;
        g_gx[(size_t)(v % 12) * N8 + (size_t)node * 8 + (v / 12)] = a;
    }
}

__global__ void gconv64_k(const float* __restrict__ feat, float* __restrict__ out, int N) {
    int node = blockIdx.x * (blockDim.x >> 5) + (threadIdx.x >> 5);
    if (node >= N) return;
    int lane = threadIdx.x & 31;
    int s = g_rowptr[node], e = g_rowptr[node + 1];
    float ax = 0.f, ay = 0.f;
    int i = s;
    for (; i + 1 < e; i += 2) {
        int s0 = __ldg(&g_srcs[i]), s1 = __ldg(&g_srcs[i + 1]);
        float w0 = __ldg(&g_ws[i]), w1 = __ldg(&g_ws[i + 1]);
        float2 f0 = __ldg(((const float2*)(feat + (size_t)s0 * 64)) + lane);
        float2 f1 = __ldg(((const float2*)(feat + (size_t)s1 * 64)) + lane);
        ax += w0 * f0.x; ay += w0 * f0.y;
        ax += w1 * f1.x; ay += w1 * f1.y;
    }
    if (i < e) {
        int s0 = __ldg(&g_srcs[i]);
        float w0 = __ldg(&g_ws[i]);
        float2 f0 = __ldg(((const float2*)(feat + (size_t)s0 * 64)) + lane);
        ax += w0 * f0.x; ay += w0 * f0.y;
    }
    ((float2*)(out + (size_t)node * 64))[lane] = make_float2(ax, ay);
}

// aggregate two 64-col tables in one edge pass -> out row of 128 ([a | b])
__global__ void gconv_dual_k(const float* __restrict__ fa, const float* __restrict__ fb,
                             float* __restrict__ out, int N) {
    int node = blockIdx.x * (blockDim.x >> 5) + (threadIdx.x >> 5);
    if (node >= N) return;
    int lane = threadIdx.x & 31;
    int s = g_rowptr[node], e = g_rowptr[node + 1];
    float ax = 0.f, ay = 0.f, bx = 0.f, by = 0.f;
    int i = s;
    for (; i + 1 < e; i += 2) {
        int s0 = __ldg(&g_srcs[i]), s1 = __ldg(&g_srcs[i + 1]);
        float w0 = __ldg(&g_ws[i]), w1 = __ldg(&g_ws[i + 1]);
        float2 fa0 = __ldg(((const float2*)(fa + (size_t)s0 * 64)) + lane);
        float2 fb0 = __ldg(((const float2*)(fb + (size_t)s0 * 64)) + lane);
        float2 fa1 = __ldg(((const float2*)(fa + (size_t)s1 * 64)) + lane);
        float2 fb1 = __ldg(((const float2*)(fb + (size_t)s1 * 64)) + lane);
        ax += w0 * fa0.x; ay += w0 * fa0.y; bx += w0 * fb0.x; by += w0 * fb0.y;
        ax += w1 * fa1.x; ay += w1 * fa1.y; bx += w1 * fb1.x; by += w1 * fb1.y;
    }
    if (i < e) {
        int s0 = __ldg(&g_srcs[i]);
        float w0 = __ldg(&g_ws[i]);
        float2 fa0 = __ldg(((const float2*)(fa + (size_t)s0 * 64)) + lane);
        float2 fb0 = __ldg(((const float2*)(fb + (size_t)s0 * 64)) + lane);
        ax += w0 * fa0.x; ay += w0 * fa0.y; bx += w0 * fb0.x; by += w0 * fb0.y;
    }
    ((float2*)(out + (size_t)node * 128))[lane]       = make_float2(ax, ay);
    ((float2*)(out + (size_t)node * 128 + 64))[lane]  = make_float2(bx, by);
}

// ============ GEMM core macro pieces: 64 rows x 64 cols tile, 256 threads ============
// thread tile 4x4, k-unroll 4, W and A staged in shared (K x 64 each, K mult of 4)

// fused gate GEMM: rz = sigmoid([A1|A2] @ W + b)
// grid.y selects column half: cy=0 -> cols 0..63 -> rh = sigmoid*h; cy=1 -> cols 64..127 -> z
__global__ void __launch_bounds__(256, 4) gate_kernel(
        const float* __restrict__ A1, int lda1, int K1,
        const float* __restrict__ A2, int lda2, int K2,
        const float* __restrict__ W, const float* __restrict__ bias,
        const float* __restrict__ h,
        float* __restrict__ rh, float* __restrict__ z, int nrows) {
    extern __shared__ float sh[];
    const int K = K1 + K2;
    float* SW = sh;          // K x 64
    float* SA = sh + K * 64; // 64 x K
    int tid = threadIdx.x;
    int cy = blockIdx.y;
    for (int idx = tid; idx < K * 64; idx += 256) {
        int k = idx >> 6, c = idx & 63;
        SW[idx] = W[k * 128 + cy * 64 + c];
    }
    int row0 = blockIdx.x * 64;
    for (int idx = tid; idx < 64 * K; idx += 256) {
        int r = idx / K, k = idx - r * K;
        int grow = row0 + r;
        float v = 0.f;
        if (grow < nrows)
            v = (k < K1) ? __ldg(&A1[(size_t)grow * lda1 + k])
                         : __ldg(&A2[(size_t)grow * lda2 + (k - K1)]);
        SA[r * K + k] = v;
    }
    __syncthreads();
    int colg = (tid & 15) * 4, rowg = (tid >> 4) * 4;
    float acc[4][4];
#pragma unroll
    for (int r = 0; r < 4; r++) { acc[r][0] = acc[r][1] = acc[r][2] = acc[r][3] = 0.f; }
#pragma unroll 2
    for (int k = 0; k < K; k += 4) {
        float4 w0 = *(const float4*)&SW[(k + 0) * 64 + colg];
        float4 w1 = *(const float4*)&SW[(k + 1) * 64 + colg];
        float4 w2 = *(const float4*)&SW[(k + 2) * 64 + colg];
        float4 w3 = *(const float4*)&SW[(k + 3) * 64 + colg];
#pragma unroll
        for (int r = 0; r < 4; r++) {
            float4 a = *(const float4*)&SA[(rowg + r) * K + k];
            acc[r][0] += a.x * w0.x; acc[r][1] += a.x * w0.y; acc[r][2] += a.x * w0.z; acc[r][3] += a.x * w0.w;
            acc[r][0] += a.y * w1.x; acc[r][1] += a.y * w1.y; acc[r][2] += a.y * w1.z; acc[r][3] += a.y * w1.w;
            acc[r][0] += a.z * w2.x; acc[r][1] += a.z * w2.y; acc[r][2] += a.z * w2.z; acc[r][3] += a.z * w2.w;
            acc[r][0] += a.w * w3.x; acc[r][1] += a.w * w3.y; acc[r][2] += a.w * w3.z; acc[r][3] += a.w * w3.w;
        }
    }
    float4 b4 = *(const float4*)&bias[cy * 64 + colg];
#pragma unroll
    for (int r = 0; r < 4; r++) {
        int grow = row0 + rowg + r;
        if (grow >= nrows) break;
        float4 v;
        v.x = sigmoid_fast(acc[r][0] + b4.x);
        v.y = sigmoid_fast(acc[r][1] + b4.y);
        v.z = sigmoid_fast(acc[r][2] + b4.z);
        v.w = sigmoid_fast(acc[r][3] + b4.w);
        if (cy == 0) {
            float4 h4 = *(const float4*)&h[(size_t)grow * 64 + colg];
            v.x *= h4.x; v.y *= h4.y; v.z *= h4.z; v.w *= h4.w;
            *(float4*)&rh[(size_t)grow * 64 + colg] = v;
        } else {
            *(float4*)&z[(size_t)grow * 64 + colg] = v;
        }
    }
}

// fused candidate GEMM: c = tanh([A1|A2] @ W + b); h = z*h + (1-z)*c
__global__ void __launch_bounds__(256, 4) cand_kernel(
        const float* __restrict__ A1, int lda1, int K1,
        const float* __restrict__ A2, int lda2, int K2,
        const float* __restrict__ W, const float* __restrict__ bias,
        const float* __restrict__ z,
        float* __restrict__ h, int nrows) {
    extern __shared__ float sh[];
    const int K = K1 + K2;
    float* SW = sh;          // K x 64
    float* SA = sh + K * 64; // 64 x K
    int tid = threadIdx.x;
    for (int idx = tid; idx < K * 64; idx += 256) SW[idx] = W[idx];
    int row0 = blockIdx.x * 64;
    for (int idx = tid; idx < 64 * K; idx += 256) {
        int r = idx / K, k = idx - r * K;
        int grow = row0 + r;
        float v = 0.f;
        if (grow < nrows)
            v = (k < K1) ? __ldg(&A1[(size_t)grow * lda1 + k])
                         : __ldg(&A2[(size_t)grow * lda2 + (k - K1)]);
        SA[r * K + k] = v;
    }
    __syncthreads();
    int colg = (tid & 15) * 4, rowg = (tid >> 4) * 4;
    float acc[4][4];
#pragma unroll
    for (int r = 0; r < 4; r++) { acc[r][0] = acc[r][1] = acc[r][2] = acc[r][3] = 0.f; }
#pragma unroll 2
    for (int k = 0; k < K; k += 4) {
        float4 w0 = *(const float4*)&SW[(k + 0) * 64 + colg];
        float4 w1 = *(const float4*)&SW[(k + 1) * 64 + colg];
        float4 w2 = *(const float4*)&SW[(k + 2) * 64 + colg];
        float4 w3 = *(const float4*)&SW[(k + 3) * 64 + colg];
#pragma unroll
        for (int r = 0; r < 4; r++) {
            float4 a = *(const float4*)&SA[(rowg + r) * K + k];
            acc[r][0] += a.x * w0.x; acc[r][1] += a.x * w0.y; acc[r][2] += a.x * w0.z; acc[r][3] += a.x * w0.w;
            acc[r][0] += a.y * w1.x; acc[r][1] += a.y * w1.y; acc[r][2] += a.y * w1.z; acc[r][3] += a.y * w1.w;
            acc[r][0] += a.z * w2.x; acc[r][1] += a.z * w2.y; acc[r][2] += a.z * w2.z; acc[r][3] += a.z * w2.w;
            acc[r][0] += a.w * w3.x; acc[r][1] += a.w * w3.y; acc[r][2] += a.w * w3.z; acc[r][3] += a.w * w3.w;
        }
    }
    float4 b4 = *(const float4*)&bias[colg];
#pragma unroll
    for (int r = 0; r < 4; r++) {
        int grow = row0 + rowg + r;
        if (grow >= nrows) break;
        float4 c4;
        c4.x = tanh_fast(acc[r][0] + b4.x);
        c4.y = tanh_fast(acc[r][1] + b4.y);
        c4.z = tanh_fast(acc[r][2] + b4.z);
        c4.w = tanh_fast(acc[r][3] + b4.w);
        float4 z4 = *(const float4*)&z[(size_t)grow * 64 + colg];
        float4 h4 = *(const float4*)&h[(size_t)grow * 64 + colg];
        h4.x = z4.x * h4.x + (1.f - z4.x) * c4.x;
        h4.y = z4.y * h4.y + (1.f - z4.y) * c4.y;
        h4.z = z4.z * h4.z + (1.f - z4.z) * c4.z;
        h4.w = z4.w * h4.w + (1.f - z4.w) * c4.w;
        *(float4*)&h[(size_t)grow * 64 + colg] = h4;
    }
}

// ---------------- output: out = h1 @ Wout + bout (Wout is 64x1) ----------------
__global__ void out_kernel(const float* __restrict__ h1, const float* __restrict__ Wout,
                           const float* __restrict__ bout, float* __restrict__ out, int N) {
    int node = blockIdx.x * (blockDim.x >> 5) + (threadIdx.x >> 5);
    if (node >= N) return;
    int lane = threadIdx.x & 31;
    float v = h1[(size_t)node * 64 + lane] * __ldg(&Wout[lane]) +
              h1[(size_t)node * 64 + lane + 32] * __ldg(&Wout[lane + 32]);
#pragma unroll
    for (int o = 16; o > 0; o >>= 1) v += __shfl_xor_sync(0xffffffffu, v, o);
    if (lane == 0) out[node] = v + bout[0];
}

// ---------------- launch ----------------
extern "C" void kernel_launch(void* const* d_in, const int* in_sizes, int n_in,
                              void* d_out, int out_size) {
    const float* x   = (const float*)d_in[0];
    const int*   ei  = (const int*)d_in[1];
    const float* ew  = (const float*)d_in[2];
    const float* Wg0 = (const float*)d_in[3];
    const float* bg0 = (const float*)d_in[4];
    const float* Wc0 = (const float*)d_in[5];
    const float* bc0 = (const float*)d_in[6];
    const float* Wg1 = (const float*)d_in[7];
    const float* bg1 = (const float*)d_in[8];
    const float* Wc1 = (const float*)d_in[9];
    const float* bc1 = (const float*)d_in[10];
    const float* Wout = (const float*)d_in[11];
    const float* bout = (const float*)d_in[12];

    int N = in_sizes[0] / 96;   // F=8, T=12
    int E = in_sizes[2];
    if (N > NMAX || E > EMAX) return;
    const int* src = ei;
    const int* dst = ei + E;

    float *p_gx, *p_h0, *p_h1, *p_gpair, *p_rh, *p_grh, *p_z;
    cudaGetSymbolAddress((void**)&p_gx, g_gx);
    cudaGetSymbolAddress((void**)&p_h0, g_h0);
    cudaGetSymbolAddress((void**)&p_h1, g_h1);
    cudaGetSymbolAddress((void**)&p_gpair, g_gpair);
    cudaGetSymbolAddress((void**)&p_rh, g_rh);
    cudaGetSymbolAddress((void**)&p_grh, g_grh);
    cudaGetSymbolAddress((void**)&p_z, g_z);

    cudaFuncSetAttribute(gate_kernel, cudaFuncAttributeMaxDynamicSharedMemorySize, 66560);
    cudaFuncSetAttribute(cand_kernel, cudaFuncAttributeMaxDynamicSharedMemorySize, 66560);

    // launch order chosen so launch #6 (ncu -s 5 -c 1) is the first gate GEMM
    init_kernel<<<512, 256>>>(N);                       // 1
    hist_kernel<<<(E + 255) / 256, 256>>>(dst, E);      // 2
    scan_kernel<<<1, 1024>>>(N);                        // 3 (also writes g_off)
    scatter_kernel<<<(E + 255) / 256, 256>>>(src, dst, ew, E);  // 4

    int gblocks = (N + 7) / 8;
    gconv_x<<<gblocks, 256>>>(x, N);                    // 5 (t-major output)

    size_t N8 = (size_t)N * 8;
    int rb = (N + 63) / 64;
    dim3 gate_grid(rb, 2);
    size_t sm72  = (size_t)72 * 64 * 4 * 2;    // 36864
    size_t sm128 = (size_t)128 * 64 * 4 * 2;   // 65536

    for (int t = 0; t < 12; t++) {
        // ---- cell 0 ----  (gconv(h0_{t-1}) lives in gpair[:, 0:64] from prior dual pass)
        gate_kernel<<<gate_grid, 256, sm72>>>(p_gx + (size_t)t * N8, 8, 8,
                                              p_gpair, 128, 64,
                                              Wg0, bg0, p_h0, p_rh, p_z, N);
        gconv64_k<<<gblocks, 256>>>(p_rh, p_grh, N);
        cand_kernel<<<rb, 256, sm72>>>(p_gx + (size_t)t * N8, 8, 8,
                                       p_grh, 64, 64,
                                       Wc0, bc0, p_z, p_h0, N);  // h0 <- new h0
        // ---- cell 1 ----
        gconv_dual_k<<<gblocks, 256>>>(p_h0, p_h1, p_gpair, N);  // [gconv(h0_new) | gconv(h1)]
        gate_kernel<<<gate_grid, 256, sm128>>>(p_gpair, 128, 64,
                                               p_gpair + 64, 128, 64,
                                               Wg1, bg1, p_h1, p_rh, p_z, N);
        gconv64_k<<<gblocks, 256>>>(p_rh, p_grh, N);
        cand_kernel<<<rb, 256, sm128>>>(p_gpair, 128, 64,
                                        p_grh, 64, 64,
                                        Wc1, bc1, p_z, p_h1, N);  // h1 <- new h1
    }

    out_kernel<<<gblocks, 256>>>(p_h1, Wout, bout, (float*)d_out, N);
}